// round 17
// baseline (speedup 1.0000x reference)
#include <cuda_runtime.h>
#include <cstdint>

// ============================================================================
// out = adj @ (x @ W)
//   x   [16384, 2048] f32  (d_in[0])
//   adj [16384,16384] f32  (d_in[1])
//   W   [ 2048,  512] f32  (d_in[2])
//   out [16384,  512] f32
//
// R15 base: fused producer/consumer kernel (512 GEMM1 h-tile producers +
// 2048 split-K=4 GEMM2 consumers gated on per-split counters), tf32
// mma.sync, 64x64 warp tiles, 3-stage cp.async with MMA-interleaved issue,
// frag double-buffering, 2 CTAs/SM.
// Round 16: consumers accumulate DIRECTLY into out via atomicAdd (REDG)
// instead of writing 128MB partials + separate reduce kernel. One tiny
// zero kernel clears out + flags. Removes ~30us serial reduce phase and
// 224MB of partial traffic.
// ============================================================================

#define BM 128
#define BN 128
#define BK 32
#define NTHREADS 128
#define NCOLS 512
#define NROWS 16384
#define SA 36                  // A smem row stride (floats): 32 + 4 pad
#define SB 136                 // B smem row stride (floats): 128 + 8 pad
#define NSTAGE 3
#define NSPLIT 4               // GEMM2 K-splits
#define PROD_CTAS 512          // GEMM1: 128 m-tiles x 4 n-tiles
#define PROD_PER_SPLIT 128     // producers covering one split's h rows

static constexpr int A_STAGE_F   = BM * SA;                 // 4608 floats
static constexpr int B_STAGE_F   = BK * SB;                 // 4352 floats
static constexpr int STAGE_F     = A_STAGE_F + B_STAGE_F;   // 8960 floats
static constexpr int SMEM_BYTES  = NSTAGE * STAGE_F * 4;    // 107520 B
static constexpr size_t OUT_ELEMS = (size_t)NROWS * NCOLS;  // 8388608

__device__ float g_h[OUT_ELEMS];                            // 32 MB scratch (h)
__device__ int   g_cnt[NSPLIT];                             // producer counters

__device__ __forceinline__ uint32_t f2tf(float f) {
    uint32_t u;
    asm("cvt.rna.tf32.f32 %0, %1;" : "=r"(u) : "f"(f));
    return u;
}
__device__ __forceinline__ uint32_t f2tf_u(uint32_t x) {
    return f2tf(__uint_as_float(x));
}

__device__ __forceinline__ uint32_t smem_u32(const void* p) {
    uint32_t a;
    asm("{ .reg .u64 t; cvta.to.shared.u64 t, %1; cvt.u32.u64 %0, t; }"
        : "=r"(a) : "l"(p));
    return a;
}

__device__ __forceinline__ void cp_async16(uint32_t dst, const void* src) {
    asm volatile("cp.async.cg.shared.global [%0], [%1], 16;"
                 :: "r"(dst), "l"(src));
}
__device__ __forceinline__ void cp_commit() {
    asm volatile("cp.async.commit_group;");
}
template <int N>
__device__ __forceinline__ void cp_wait() {
    asm volatile("cp.async.wait_group %0;" :: "n"(N));
}

__device__ __forceinline__ void ldsm_x4(uint32_t* r, uint32_t addr) {
    asm volatile(
        "ldmatrix.sync.aligned.m8n8.x4.shared.b16 {%0,%1,%2,%3}, [%4];"
        : "=r"(r[0]), "=r"(r[1]), "=r"(r[2]), "=r"(r[3]) : "r"(addr));
}

__device__ __forceinline__ void mma_tf32(float* d,
                                         const uint32_t* a,
                                         const uint32_t* b) {
    asm volatile(
        "mma.sync.aligned.m16n8k8.row.col.f32.tf32.tf32.f32 "
        "{%0,%1,%2,%3}, {%4,%5,%6,%7}, {%8,%9}, {%0,%1,%2,%3};"
        : "+f"(d[0]), "+f"(d[1]), "+f"(d[2]), "+f"(d[3])
        : "r"(a[0]), "r"(a[1]), "r"(a[2]), "r"(a[3]),
          "r"(b[0]), "r"(b[1]));
}

// One 128x128 output tile of C = A[BM, K] @ B[K, 512-slab].
// CVT_B: tf32-convert B fragments (h is pre-rounded for GEMM2).
// ROUND_OUT: write C tf32-pre-rounded (producers).
// ATOMIC_OUT: accumulate into C with atomicAdd/REDG (consumers).
template <bool CVT_B, bool ROUND_OUT, bool ATOMIC_OUT>
__device__ __forceinline__ void gemm_body(
    const float* __restrict__ A, const float* __restrict__ B,
    float* __restrict__ C, int niter, int ldA, int m0, int n0, float* smem) {

    const int tid  = threadIdx.x;
    const int wid  = tid >> 5;           // 0..3
    const int lane = tid & 31;
    const int q    = lane >> 2;          // 0..7
    const int t    = lane & 3;           // 0..3
    const int wm   = (wid & 1) * 64;     // 2x2 warp grid, 64x64 warp tiles
    const int wn   = (wid >> 1) * 64;

    const float* a_src = A + (size_t)(m0 + (tid >> 3)) * ldA + (tid & 7) * 4;
    const float* b_src = B + (size_t)(tid >> 5) * NCOLS + n0 + (tid & 31) * 4;
    const uint32_t smem_base = smem_u32(smem);
    const uint32_t a_dst = smem_base + ((tid >> 3) * SA + (tid & 7) * 4) * 4;
    const uint32_t b_dst = smem_base + (A_STAGE_F + (tid >> 5) * SB + (tid & 31) * 4) * 4;

    // one quarter of a stage's loads: parts 0/1 = A halves, 2/3 = B halves
    auto issue_chunk = [&](int sbuf, int kb, int part) {
        const uint32_t soff = (uint32_t)(sbuf * STAGE_F * 4);
        if (part < 2) {
            const float* as = a_src + (size_t)kb * BK;
            #pragma unroll
            for (int i = 0; i < 4; ++i) {
                int c = part * 4 + i;
                cp_async16(a_dst + soff + c * (16 * SA * 4), as + (size_t)c * 16 * ldA);
            }
        } else {
            const float* bs = b_src + (size_t)kb * BK * NCOLS;
            #pragma unroll
            for (int i = 0; i < 4; ++i) {
                int c = (part - 2) * 4 + i;
                cp_async16(b_dst + soff + c * (4 * SB * 4), bs + (size_t)c * 4 * NCOLS);
            }
        }
    };
    auto issue_all = [&](int sbuf, int kb) {
        #pragma unroll
        for (int p = 0; p < 4; ++p) issue_chunk(sbuf, kb, p);
    };

    float acc[4][8][4];
    #pragma unroll
    for (int i = 0; i < 4; ++i)
        #pragma unroll
        for (int j = 0; j < 8; ++j)
            #pragma unroll
            for (int r = 0; r < 4; ++r)
                acc[i][j][r] = 0.0f;

    issue_all(0, 0); cp_commit();
    issue_all(1, 1); cp_commit();

    // ldmatrix lane addressing: row = wm + mi*16 + (lane&15), col4 = (lane>>4)*4
    const uint32_t a_lds = smem_base +
        (((wm + (lane & 15)) * SA + (lane >> 4) * 4) * 4);
    const int boff = A_STAGE_F + t * SB + wn + q;

    uint32_t af[2][4][4];
    uint32_t bf[2][8][2];

    int buf = 0;
    for (int it = 0; it < niter; ++it) {
        cp_wait<1>();
        __syncthreads();

        const uint32_t a_stage = a_lds + (uint32_t)(buf * STAGE_F * 4);
        const float*   Bc      = smem + buf * STAGE_F;

        auto load_frags = [&](int k, int pb) {
            #pragma unroll
            for (int mi = 0; mi < 4; ++mi) {
                ldsm_x4(af[pb][mi], a_stage + (uint32_t)((mi * 16 * SA + k * 8) * 4));
                af[pb][mi][0] = f2tf_u(af[pb][mi][0]);
                af[pb][mi][1] = f2tf_u(af[pb][mi][1]);
                af[pb][mi][2] = f2tf_u(af[pb][mi][2]);
                af[pb][mi][3] = f2tf_u(af[pb][mi][3]);
            }
            #pragma unroll
            for (int ni = 0; ni < 8; ++ni) {
                const float* bb = Bc + boff + k * (8 * SB) + ni * 8;
                if (CVT_B) {
                    bf[pb][ni][0] = f2tf(bb[0]);
                    bf[pb][ni][1] = f2tf(bb[4 * SB]);
                } else {
                    bf[pb][ni][0] = ((const uint32_t*)bb)[0];
                    bf[pb][ni][1] = ((const uint32_t*)bb)[4 * SB];
                }
            }
        };

        // critical path first: k8=0 fragments hit an empty MIO queue
        load_frags(0, 0);

        const bool do_issue = (it + 2 < niter);
        int nb = buf + 2; if (nb >= NSTAGE) nb -= NSTAGE;

        #pragma unroll
        for (int k8 = 0; k8 < 4; ++k8) {
            const int cur = k8 & 1;
            if (k8 < 3) load_frags(k8 + 1, cur ^ 1);
            #pragma unroll
            for (int mi = 0; mi < 4; ++mi)
                #pragma unroll
                for (int ni = 0; ni < 8; ++ni)
                    mma_tf32(acc[mi][ni], af[cur][mi], bf[cur][ni]);
            // interleave a quarter of next-next stage's loads behind the MMAs
            if (do_issue) issue_chunk(nb, it + 2, k8);
        }
        cp_commit();

        if (++buf >= NSTAGE) buf = 0;
    }

    // ---- epilogue ----
    #pragma unroll
    for (int mi = 0; mi < 4; ++mi) {
        #pragma unroll
        for (int ni = 0; ni < 8; ++ni) {
            const int m = m0 + wm + mi * 16 + q;
            const int n = n0 + wn + ni * 8 + 2 * t;
            float v0 = acc[mi][ni][0], v1 = acc[mi][ni][1];
            float v2 = acc[mi][ni][2], v3 = acc[mi][ni][3];
            if (ATOMIC_OUT) {
                float* p0 = C + (size_t)m * NCOLS + n;
                float* p1 = C + (size_t)(m + 8) * NCOLS + n;
                atomicAdd(p0,     v0);
                atomicAdd(p0 + 1, v1);
                atomicAdd(p1,     v2);
                atomicAdd(p1 + 1, v3);
            } else {
                if (ROUND_OUT) {
                    v0 = __uint_as_float(f2tf(v0));
                    v1 = __uint_as_float(f2tf(v1));
                    v2 = __uint_as_float(f2tf(v2));
                    v3 = __uint_as_float(f2tf(v3));
                }
                *(float2*)(C + (size_t)m * NCOLS + n)       = make_float2(v0, v1);
                *(float2*)(C + (size_t)(m + 8) * NCOLS + n) = make_float2(v2, v3);
            }
        }
    }
}

// ---------------------------------------------------------------------------
// Fused kernel: blockIdx.x < 512 -> GEMM1 producer tile (h), else GEMM2
// consumer tile gated on its split's producer counter, accumulating into out.
// ---------------------------------------------------------------------------
__global__ void __launch_bounds__(NTHREADS, 2)
fused_kernel(const float* __restrict__ x, const float* __restrict__ adj,
             const float* __restrict__ W, float* __restrict__ out) {
    extern __shared__ float smem[];
    const int b = blockIdx.x;

    if (b < PROD_CTAS) {
        // ---- producer: h tile. z-major order so split z's producers are
        //      the contiguous block b in [z*128, (z+1)*128). ----
        const int z  = b >> 7;
        const int mt = (z << 5) | ((b >> 2) & 31);
        const int nt = b & 3;
        gemm_body<true, true, false>(x, W, g_h, 2048 / BK, 2048,
                                     mt * BM, nt * BN, smem);
        __threadfence();          // publish h stores
        __syncthreads();
        if (threadIdx.x == 0) atomicAdd(&g_cnt[z], 1);
    } else {
        // ---- consumer: GEMM2 split-K tile, z ascending ----
        const int qq = b - PROD_CTAS;
        const int z  = qq >> 9;
        const int r  = qq & 511;
        const int mt = r >> 2;
        const int nt = r & 3;

        if (threadIdx.x == 0) {
            volatile int* c = g_cnt;
            while (c[z] < PROD_PER_SPLIT)
                asm volatile("nanosleep.u32 1024;");
        }
        __syncthreads();
        __threadfence();          // acquire: order h reads after flag

        const float* A = adj + (size_t)z * (NROWS / NSPLIT);
        const float* B = g_h + (size_t)z * (NROWS / NSPLIT) * NCOLS;
        gemm_body<false, false, true>(A, B, out, (NROWS / NSPLIT) / BK, NROWS,
                                      mt * BM, nt * BN, smem);
    }
}

// zero out (float4 stores) + reset producer counters
__global__ void __launch_bounds__(256)
zero_kernel(float* __restrict__ out) {
    size_t i = ((size_t)blockIdx.x * 256 + threadIdx.x) * 4;
    *(float4*)(out + i) = make_float4(0.f, 0.f, 0.f, 0.f);
    if (blockIdx.x == 0 && threadIdx.x < NSPLIT) g_cnt[threadIdx.x] = 0;
}

// ---------------------------------------------------------------------------
extern "C" void kernel_launch(void* const* d_in, const int* in_sizes, int n_in,
                              void* d_out, int out_size) {
    const float* x   = (const float*)d_in[0];   // [16384, 2048]
    const float* adj = (const float*)d_in[1];   // [16384, 16384]
    const float* W   = (const float*)d_in[2];   // [2048, 512]
    float* out = (float*)d_out;                 // [16384, 512]

    cudaFuncSetAttribute(fused_kernel,
                         cudaFuncAttributeMaxDynamicSharedMemorySize, SMEM_BYTES);

    // zero out + flags (graph replays reuse device globals)
    zero_kernel<<<(int)(OUT_ELEMS / (256 * 4)), 256>>>(out);

    // producers (512) + consumers (2048) in one launch; consumers REDG into out
    fused_kernel<<<PROD_CTAS + NSPLIT * 512, NTHREADS, SMEM_BYTES>>>(
        x, adj, W, out);
}